// round 10
// baseline (speedup 1.0000x reference)
#include <cuda_runtime.h>
#include <cuda_fp16.h>
#include <math.h>
#include <stdint.h>

#define BSZ 131072
#define TTR 10
#define KF 320          // padded feature dim (300 -> 320)
#define HID 1024
#define NUM_ELEM 118

// ---- scratch (device globals; no runtime allocation) ----
__device__ __half g_feat[(size_t)BSZ * KF];
__device__ __half g_h1[(size_t)BSZ * HID];
__device__ __half g_w1t[(size_t)HID * KF];    // W1^T [n][k], zero-padded
__device__ __half g_w2t[(size_t)HID * HID];   // W2^T [n][k]

// ---- helpers ----
__device__ __forceinline__ void mma16(float* c, const uint32_t* a,
                                      uint32_t b0, uint32_t b1) {
    asm volatile(
        "mma.sync.aligned.m16n8k16.row.col.f32.f16.f16.f32 "
        "{%0,%1,%2,%3}, {%4,%5,%6,%7}, {%8,%9}, {%0,%1,%2,%3};"
        : "+f"(c[0]), "+f"(c[1]), "+f"(c[2]), "+f"(c[3])
        : "r"(a[0]), "r"(a[1]), "r"(a[2]), "r"(a[3]), "r"(b0), "r"(b1));
}
__device__ __forceinline__ void ldsm4(uint32_t* r, uint32_t addr) {
    asm volatile("ldmatrix.sync.aligned.m8n8.x4.shared.b16 {%0,%1,%2,%3}, [%4];"
                 : "=r"(r[0]), "=r"(r[1]), "=r"(r[2]), "=r"(r[3]) : "r"(addr));
}
__device__ __forceinline__ void cp16(uint32_t dst, const void* src) {
    asm volatile("cp.async.cg.shared.global [%0], [%1], 16;" :: "r"(dst), "l"(src));
}
#define CP_COMMIT() asm volatile("cp.async.commit_group;")
#define CP_WAIT1()  asm volatile("cp.async.wait_group 1;")
#define CP_WAIT0()  asm volatile("cp.async.wait_group 0;")

// ---- prep: transpose weights to [n][k] half ----
__global__ void prep_w1t_kernel(const float* __restrict__ W1, __half* __restrict__ w1t) {
    int i = blockIdx.x * blockDim.x + threadIdx.x;
    if (i >= HID * KF) return;
    int n = i / KF, k = i - n * KF;
    w1t[i] = (k < 300) ? __float2half(W1[(size_t)k * HID + n]) : __half(0.0f);
}
__global__ void prep_w2t_kernel(const float* __restrict__ W2, __half* __restrict__ w2t) {
    int i = blockIdx.x * blockDim.x + threadIdx.x;
    if (i >= HID * HID) return;
    int n = i >> 10, k = i & 1023;
    w2t[i] = __float2half(W2[(size_t)k * HID + n]);
}
__global__ void init_out_kernel(float* __restrict__ out, const float* __restrict__ b3) {
    int i = blockIdx.x * blockDim.x + threadIdx.x;
    if (i < BSZ) out[i] = b3[0];
}

// ---- features: one warp per structure row (all lanes participate in shfl) ----
__global__ void feat_kernel(const float* __restrict__ structures,
                            const float* __restrict__ E,
                            __half* __restrict__ feat) {
    __shared__ float sE[NUM_ELEM * 10];
    for (int i = threadIdx.x; i < NUM_ELEM * 10; i += blockDim.x) sE[i] = E[i];
    __syncthreads();

    int wrow = (blockIdx.x * blockDim.x + threadIdx.x) >> 5;
    if (wrow >= BSZ) return;
    int lane = threadIdx.x & 31;

    float sv = 0.0f;
    if (lane < 30) sv = structures[(size_t)wrow * 30 + lane];

    __half* o = feat + (size_t)wrow * KF;

    #pragma unroll
    for (int i = 0; i < 10; i++) {
        int c = lane + 32 * i;
        int cc = c < 299 ? c : 299;
        int t = cc / 30;
        int r = cc - t * 30;
        float s0 = __shfl_sync(0xffffffffu, sv, 3 * t);
        float s1 = __shfl_sync(0xffffffffu, sv, 3 * t + 1);
        float s2 = __shfl_sync(0xffffffffu, sv, 3 * t + 2);
        float v = 0.0f;
        if (c < 300) {
            int ii = (int)s0;
            int jj = (int)s1;
            if (r < 10) {
                v = ii ? sE[ii * 10 + r] : 0.0f;
            } else if (r < 20) {
                v = jj ? sE[jj * 10 + (r - 10)] : 0.0f;
            } else if (ii) {
                float diff = 0.7f * (float)(r - 19) - s2;
                v = __expf(-diff * diff);
            }
        }
        o[c] = __float2half(v);
    }
}

// ---- fp16 GEMM: CTA 128x256, warp tile 64x64 (2x4), BK=64, 3-stage ----
#define BM 128
#define BN 256
#define BK 64
#define RSTR 144                         // 128B data + 16B pad per row
#define ASTAGE (BM * RSTR)               // 18432 B
#define BSTAGE (BN * RSTR)               // 36864 B
#define STAGE (ASTAGE + BSTAGE)          // 55296 B
#define NSTG 3
#define SMEM_BYTES (NSTG * STAGE + 2 * BN * 4)   // 167936 B

template <int EPI>
__global__ void __launch_bounds__(256, 1) gemm_kernel(
    const __half* __restrict__ A, int lda, int K,
    const __half* __restrict__ Bt,    // [1024][K] half (n-major)
    const float* __restrict__ bias,
    const float* __restrict__ W3,
    void* __restrict__ CoutV)
{
    extern __shared__ char smem[];
    uint32_t sbase;
    asm("{ .reg .u64 t; cvta.to.shared.u64 t, %1; cvt.u32.u64 %0, t; }"
        : "=r"(sbase) : "l"(smem));
    float* sBias = (float*)(smem + NSTG * STAGE);
    float* sW3   = sBias + BN;

    const int tid  = threadIdx.x;
    const int lane = tid & 31;
    const int wid  = tid >> 5;
    const int wm   = wid & 1;        // 2 warp rows of 64
    const int wn   = wid >> 1;       // 4 warp cols of 64
    const int g    = lane >> 2;
    const int t    = lane & 3;
    const int lr   = lane & 7;
    const int m0   = blockIdx.y * BM;
    const int n0   = blockIdx.x * BN;

    float acc[4][8][4];              // 4 m16 blocks x 8 n8 blocks
    #pragma unroll
    for (int i = 0; i < 4; i++)
        #pragma unroll
        for (int j = 0; j < 8; j++)
            #pragma unroll
            for (int k = 0; k < 4; k++) acc[i][j][k] = 0.0f;

    const int KT = K / BK;

    auto issue = [&](int kt, int buf) {
        int k0 = kt * BK;
        uint32_t ab = sbase + buf * STAGE;
        uint32_t bb = ab + ASTAGE;
        #pragma unroll
        for (int i = 0; i < 4; i++) {                 // A: 1024 chunks of 16B
            int idx = tid + (i << 8);
            int row = idx >> 3, c = idx & 7;
            cp16(ab + row * RSTR + c * 16,
                 A + (size_t)(m0 + row) * lda + k0 + c * 8);
        }
        #pragma unroll
        for (int i = 0; i < 8; i++) {                 // B: 2048 chunks of 16B
            int idx = tid + (i << 8);
            int row = idx >> 3, c = idx & 7;
            cp16(bb + row * RSTR + c * 16,
                 Bt + (size_t)(n0 + row) * K + k0 + c * 8);
        }
    };

    auto compute = [&](int buf) {
        uint32_t ab = sbase + buf * STAGE;
        uint32_t bb = ab + ASTAGE;
        #pragma unroll
        for (int ks = 0; ks < 4; ks++) {              // four k-steps of 16
            const int cb = ks * 2;
            uint32_t a[4][4];
            #pragma unroll
            for (int ms = 0; ms < 4; ms++) {
                int row = wm * 64 + ms * 16 + lr + ((lane >> 3) & 1) * 8;
                int ch  = cb + (lane >> 4);
                ldsm4(a[ms], ab + row * RSTR + ch * 16);
            }
            #pragma unroll
            for (int np = 0; np < 4; np++) {          // 4 pairs of n8 tiles
                uint32_t bfr[4];
                int row = wn * 64 + np * 16 + lr + (lane >> 4) * 8;
                int ch  = cb + ((lane >> 3) & 1);
                ldsm4(bfr, bb + row * RSTR + ch * 16);
                #pragma unroll
                for (int ms = 0; ms < 4; ms++) {
                    mma16(acc[ms][2 * np],     a[ms], bfr[0], bfr[1]);
                    mma16(acc[ms][2 * np + 1], a[ms], bfr[2], bfr[3]);
                }
            }
        }
    };

    issue(0, 0); CP_COMMIT();
    issue(1, 1); CP_COMMIT();

    for (int kt = 0; kt < KT; kt++) {
        int cur = kt - (kt / NSTG) * NSTG;            // kt % 3
        if (kt + 1 < KT) CP_WAIT1(); else CP_WAIT0();
        __syncthreads();
        if (kt + 2 < KT) {
            int nb = kt + 2;
            issue(nb, nb - (nb / NSTG) * NSTG);
            CP_COMMIT();
        }
        compute(cur);
    }

    for (int i = tid; i < BN; i += 256) {
        sBias[i] = bias[n0 + i];
        if (EPI == 1) sW3[i] = W3[n0 + i];
    }
    __syncthreads();

    if (EPI == 0) {
        __half* Cout = (__half*)CoutV;
        #pragma unroll
        for (int ms = 0; ms < 4; ms++) {
            int row = m0 + wm * 64 + ms * 16 + g;
            #pragma unroll
            for (int ns = 0; ns < 8; ns++) {
                int cl  = wn * 64 + ns * 8 + t * 2;
                int col = n0 + cl;
                __half2 v0 = __floats2half2_rn(
                    fmaxf(acc[ms][ns][0] + sBias[cl],     0.0f),
                    fmaxf(acc[ms][ns][1] + sBias[cl + 1], 0.0f));
                __half2 v1 = __floats2half2_rn(
                    fmaxf(acc[ms][ns][2] + sBias[cl],     0.0f),
                    fmaxf(acc[ms][ns][3] + sBias[cl + 1], 0.0f));
                *(__half2*)&Cout[(size_t)row * HID + col]       = v0;
                *(__half2*)&Cout[(size_t)(row + 8) * HID + col] = v1;
            }
        }
    } else {
        float* Cout = (float*)CoutV;
        #pragma unroll
        for (int ms = 0; ms < 4; ms++) {
            float r0 = 0.0f, r1 = 0.0f;
            #pragma unroll
            for (int ns = 0; ns < 8; ns++) {
                int cl = wn * 64 + ns * 8 + t * 2;
                r0 += fmaxf(acc[ms][ns][0] + sBias[cl],     0.0f) * sW3[cl]
                    + fmaxf(acc[ms][ns][1] + sBias[cl + 1], 0.0f) * sW3[cl + 1];
                r1 += fmaxf(acc[ms][ns][2] + sBias[cl],     0.0f) * sW3[cl]
                    + fmaxf(acc[ms][ns][3] + sBias[cl + 1], 0.0f) * sW3[cl + 1];
            }
            r0 += __shfl_xor_sync(0xffffffffu, r0, 1);
            r0 += __shfl_xor_sync(0xffffffffu, r0, 2);
            r1 += __shfl_xor_sync(0xffffffffu, r1, 1);
            r1 += __shfl_xor_sync(0xffffffffu, r1, 2);
            if (t == 0) {
                atomicAdd(&Cout[m0 + wm * 64 + ms * 16 + g], r0);
                atomicAdd(&Cout[m0 + wm * 64 + ms * 16 + 8 + g], r1);
            }
        }
    }
}

// ---- launch ----
extern "C" void kernel_launch(void* const* d_in, const int* in_sizes, int n_in,
                              void* d_out, int out_size) {
    const float* structures = (const float*)d_in[0];
    const float* E  = (const float*)d_in[1];
    const float* W1 = (const float*)d_in[2];
    const float* b1 = (const float*)d_in[3];
    const float* W2 = (const float*)d_in[4];
    const float* b2 = (const float*)d_in[5];
    const float* W3 = (const float*)d_in[6];
    const float* b3 = (const float*)d_in[7];
    float* out = (float*)d_out;

    __half *feat, *h1, *w1t, *w2t;
    cudaGetSymbolAddress((void**)&feat, g_feat);
    cudaGetSymbolAddress((void**)&h1,   g_h1);
    cudaGetSymbolAddress((void**)&w1t,  g_w1t);
    cudaGetSymbolAddress((void**)&w2t,  g_w2t);

    cudaFuncSetAttribute(gemm_kernel<0>, cudaFuncAttributeMaxDynamicSharedMemorySize, SMEM_BYTES);
    cudaFuncSetAttribute(gemm_kernel<1>, cudaFuncAttributeMaxDynamicSharedMemorySize, SMEM_BYTES);

    prep_w1t_kernel<<<(HID * KF + 255) / 256, 256>>>(W1, w1t);
    prep_w2t_kernel<<<(HID * HID + 255) / 256, 256>>>(W2, w2t);
    init_out_kernel<<<(BSZ + 255) / 256, 256>>>(out, b3);
    feat_kernel<<<(BSZ * 32 + 255) / 256, 256>>>(structures, E, feat);

    dim3 grid(HID / BN, BSZ / BM);   // (4, 1024)
    gemm_kernel<0><<<grid, 256, SMEM_BYTES>>>(feat, KF, KF, w1t, b1, nullptr, (void*)h1);
    gemm_kernel<1><<<grid, 256, SMEM_BYTES>>>(h1, HID, HID, w2t, b2, W3, (void*)out);
}

// round 11
// speedup vs baseline: 1.0707x; 1.0707x over previous
#include <cuda_runtime.h>
#include <cuda_fp16.h>
#include <math.h>
#include <stdint.h>

#define BSZ 131072
#define TTR 10
#define KF 320          // padded feature dim (300 -> 320)
#define HID 1024
#define NUM_ELEM 118

// ---- scratch (device globals; no runtime allocation) ----
__device__ __half g_feat[(size_t)BSZ * KF];
__device__ __half g_h1[(size_t)BSZ * HID];
__device__ __half g_w1t[(size_t)HID * KF];    // W1^T [n][k], zero-padded
__device__ __half g_w2t[(size_t)HID * HID];   // W2^T [n][k]

// ---- helpers ----
__device__ __forceinline__ void mma16(float* c, const uint32_t* a,
                                      uint32_t b0, uint32_t b1) {
    asm volatile(
        "mma.sync.aligned.m16n8k16.row.col.f32.f16.f16.f32 "
        "{%0,%1,%2,%3}, {%4,%5,%6,%7}, {%8,%9}, {%0,%1,%2,%3};"
        : "+f"(c[0]), "+f"(c[1]), "+f"(c[2]), "+f"(c[3])
        : "r"(a[0]), "r"(a[1]), "r"(a[2]), "r"(a[3]), "r"(b0), "r"(b1));
}
__device__ __forceinline__ void ldsm4(uint32_t* r, uint32_t addr) {
    asm volatile("ldmatrix.sync.aligned.m8n8.x4.shared.b16 {%0,%1,%2,%3}, [%4];"
                 : "=r"(r[0]), "=r"(r[1]), "=r"(r[2]), "=r"(r[3]) : "r"(addr));
}
__device__ __forceinline__ void cp16(uint32_t dst, const void* src) {
    asm volatile("cp.async.cg.shared.global [%0], [%1], 16;" :: "r"(dst), "l"(src));
}
#define CP_COMMIT() asm volatile("cp.async.commit_group;")
#define CP_WAIT1()  asm volatile("cp.async.wait_group 1;")
#define CP_WAIT0()  asm volatile("cp.async.wait_group 0;")

// ---- prep: transpose weights to [n][k] half ----
__global__ void prep_w1t_kernel(const float* __restrict__ W1, __half* __restrict__ w1t) {
    int i = blockIdx.x * blockDim.x + threadIdx.x;
    if (i >= HID * KF) return;
    int n = i / KF, k = i - n * KF;
    w1t[i] = (k < 300) ? __float2half(W1[(size_t)k * HID + n]) : __half(0.0f);
}
__global__ void prep_w2t_kernel(const float* __restrict__ W2, __half* __restrict__ w2t) {
    int i = blockIdx.x * blockDim.x + threadIdx.x;
    if (i >= HID * HID) return;
    int n = i >> 10, k = i & 1023;
    w2t[i] = __float2half(W2[(size_t)k * HID + n]);
}
__global__ void init_out_kernel(float* __restrict__ out, const float* __restrict__ b3) {
    int i = blockIdx.x * blockDim.x + threadIdx.x;
    if (i < BSZ) out[i] = b3[0];
}

// ---- features: one warp per structure row (all lanes participate in shfl) ----
__global__ void feat_kernel(const float* __restrict__ structures,
                            const float* __restrict__ E,
                            __half* __restrict__ feat) {
    __shared__ float sE[NUM_ELEM * 10];
    for (int i = threadIdx.x; i < NUM_ELEM * 10; i += blockDim.x) sE[i] = E[i];
    __syncthreads();

    int wrow = (blockIdx.x * blockDim.x + threadIdx.x) >> 5;
    if (wrow >= BSZ) return;
    int lane = threadIdx.x & 31;

    float sv = 0.0f;
    if (lane < 30) sv = structures[(size_t)wrow * 30 + lane];

    __half* o = feat + (size_t)wrow * KF;

    #pragma unroll
    for (int i = 0; i < 10; i++) {
        int c = lane + 32 * i;
        int cc = c < 299 ? c : 299;
        int t = cc / 30;
        int r = cc - t * 30;
        float s0 = __shfl_sync(0xffffffffu, sv, 3 * t);
        float s1 = __shfl_sync(0xffffffffu, sv, 3 * t + 1);
        float s2 = __shfl_sync(0xffffffffu, sv, 3 * t + 2);
        float v = 0.0f;
        if (c < 300) {
            int ii = (int)s0;
            int jj = (int)s1;
            if (r < 10) {
                v = ii ? sE[ii * 10 + r] : 0.0f;
            } else if (r < 20) {
                v = jj ? sE[jj * 10 + (r - 10)] : 0.0f;
            } else if (ii) {
                float diff = 0.7f * (float)(r - 19) - s2;
                v = __expf(-diff * diff);
            }
        }
        o[c] = __float2half(v);
    }
}

// ---- fp16 GEMM: BM=128, BN=128, warp 32x64, 2 CTAs/SM, 3-stage cp.async ----
// compute() software-pipelines ldsm -> mma at register level.
#define BM 128
#define BN 128
#define BK 64
#define RSTR 144                         // 128B data + 16B pad per row
#define ASTAGE (BM * RSTR)               // 18432 B
#define BSTAGE (BN * RSTR)               // 18432 B
#define STAGE (ASTAGE + BSTAGE)          // 36864 B
#define NSTG 3
#define SMEM_BYTES (NSTG * STAGE + 2 * BN * 4)   // 111616 B -> 2 CTAs/SM

template <int EPI>
__global__ void __launch_bounds__(256, 2) gemm_kernel(
    const __half* __restrict__ A, int lda, int K,
    const __half* __restrict__ Bt,    // [1024][K] half (n-major)
    const float* __restrict__ bias,
    const float* __restrict__ W3,
    void* __restrict__ CoutV)
{
    extern __shared__ char smem[];
    uint32_t sbase;
    asm("{ .reg .u64 t; cvta.to.shared.u64 t, %1; cvt.u32.u64 %0, t; }"
        : "=r"(sbase) : "l"(smem));
    float* sBias = (float*)(smem + NSTG * STAGE);
    float* sW3   = sBias + BN;

    const int tid  = threadIdx.x;
    const int lane = tid & 31;
    const int wid  = tid >> 5;
    const int wm   = wid & 3;        // 4 warp rows of 32
    const int wn   = wid >> 2;       // 2 warp cols of 64
    const int g    = lane >> 2;
    const int t    = lane & 3;
    const int lr   = lane & 7;
    const int m0   = blockIdx.y * BM;
    const int n0   = blockIdx.x * BN;

    float acc[2][8][4];
    #pragma unroll
    for (int i = 0; i < 2; i++)
        #pragma unroll
        for (int j = 0; j < 8; j++)
            #pragma unroll
            for (int k = 0; k < 4; k++) acc[i][j][k] = 0.0f;

    const int KT = K / BK;

    auto issue = [&](int kt, int buf) {
        int k0 = kt * BK;
        uint32_t ab = sbase + buf * STAGE;
        uint32_t bb = ab + ASTAGE;
        #pragma unroll
        for (int i = 0; i < 4; i++) {                 // A: 1024 chunks of 16B
            int idx = tid + (i << 8);
            int row = idx >> 3, c = idx & 7;
            cp16(ab + row * RSTR + c * 16,
                 A + (size_t)(m0 + row) * lda + k0 + c * 8);
        }
        #pragma unroll
        for (int i = 0; i < 4; i++) {                 // B: 1024 chunks of 16B
            int idx = tid + (i << 8);
            int row = idx >> 3, c = idx & 7;
            cp16(bb + row * RSTR + c * 16,
                 Bt + (size_t)(n0 + row) * K + k0 + c * 8);
        }
    };

    auto compute = [&](int buf) {
        uint32_t ab = sbase + buf * STAGE;
        uint32_t bb = ab + ASTAGE;

        auto lda_ = [&](uint32_t* r, int ms, int ks) {
            int row = wm * 32 + ms * 16 + lr + ((lane >> 3) & 1) * 8;
            int ch  = ks * 2 + (lane >> 4);
            ldsm4(r, ab + row * RSTR + ch * 16);
        };
        auto ldb_ = [&](uint32_t* r, int np, int ks) {
            int row = wn * 64 + np * 16 + lr + (lane >> 4) * 8;
            int ch  = ks * 2 + ((lane >> 3) & 1);
            ldsm4(r, bb + row * RSTR + ch * 16);
        };

        uint32_t a[2][4], an[2][4];     // current / next-kstep A frags
        uint32_t bc[4], bn[4];          // current / next B frags

        lda_(a[0], 0, 0); lda_(a[1], 1, 0);
        ldb_(bc, 0, 0);

        #pragma unroll
        for (int ks = 0; ks < 4; ks++) {
            #pragma unroll
            for (int np = 0; np < 4; np++) {
                // prefetch next B fragment (and next-kstep A after first mma group)
                if (np < 3)            ldb_(bn, np + 1, ks);
                else if (ks < 3)       ldb_(bn, 0, ks + 1);
                if (np == 0 && ks < 3) { lda_(an[0], 0, ks + 1); lda_(an[1], 1, ks + 1); }

                mma16(acc[0][2 * np],     a[0], bc[0], bc[1]);
                mma16(acc[0][2 * np + 1], a[0], bc[2], bc[3]);
                mma16(acc[1][2 * np],     a[1], bc[0], bc[1]);
                mma16(acc[1][2 * np + 1], a[1], bc[2], bc[3]);

                if (!(ks == 3 && np == 3)) {
                    bc[0] = bn[0]; bc[1] = bn[1]; bc[2] = bn[2]; bc[3] = bn[3];
                }
            }
            if (ks < 3) {
                #pragma unroll
                for (int q = 0; q < 4; q++) { a[0][q] = an[0][q]; a[1][q] = an[1][q]; }
            }
        }
    };

    issue(0, 0); CP_COMMIT();
    issue(1, 1); CP_COMMIT();

    for (int kt = 0; kt < KT; kt++) {
        int cur = kt - (kt / NSTG) * NSTG;            // kt % 3
        if (kt + 1 < KT) CP_WAIT1(); else CP_WAIT0();
        __syncthreads();
        if (kt + 2 < KT) {
            int nb = kt + 2;
            issue(nb, nb - (nb / NSTG) * NSTG);
            CP_COMMIT();
        }
        compute(cur);
    }

    for (int i = tid; i < BN; i += 256) {
        sBias[i] = bias[n0 + i];
        if (EPI == 1) sW3[i] = W3[n0 + i];
    }
    __syncthreads();

    if (EPI == 0) {
        __half* Cout = (__half*)CoutV;
        #pragma unroll
        for (int ms = 0; ms < 2; ms++) {
            int row = m0 + wm * 32 + ms * 16 + g;
            #pragma unroll
            for (int ns = 0; ns < 8; ns++) {
                int cl  = wn * 64 + ns * 8 + t * 2;
                int col = n0 + cl;
                __half2 v0 = __floats2half2_rn(
                    fmaxf(acc[ms][ns][0] + sBias[cl],     0.0f),
                    fmaxf(acc[ms][ns][1] + sBias[cl + 1], 0.0f));
                __half2 v1 = __floats2half2_rn(
                    fmaxf(acc[ms][ns][2] + sBias[cl],     0.0f),
                    fmaxf(acc[ms][ns][3] + sBias[cl + 1], 0.0f));
                *(__half2*)&Cout[(size_t)row * HID + col]       = v0;
                *(__half2*)&Cout[(size_t)(row + 8) * HID + col] = v1;
            }
        }
    } else {
        float* Cout = (float*)CoutV;
        float racc[2][2] = {{0.0f, 0.0f}, {0.0f, 0.0f}};
        #pragma unroll
        for (int ms = 0; ms < 2; ms++) {
            #pragma unroll
            for (int ns = 0; ns < 8; ns++) {
                int cl = wn * 64 + ns * 8 + t * 2;
                racc[ms][0] += fmaxf(acc[ms][ns][0] + sBias[cl],     0.0f) * sW3[cl]
                             + fmaxf(acc[ms][ns][1] + sBias[cl + 1], 0.0f) * sW3[cl + 1];
                racc[ms][1] += fmaxf(acc[ms][ns][2] + sBias[cl],     0.0f) * sW3[cl]
                             + fmaxf(acc[ms][ns][3] + sBias[cl + 1], 0.0f) * sW3[cl + 1];
            }
        }
        #pragma unroll
        for (int ms = 0; ms < 2; ms++) {
            #pragma unroll
            for (int rp = 0; rp < 2; rp++) {
                float p = racc[ms][rp];
                p += __shfl_xor_sync(0xffffffffu, p, 1);
                p += __shfl_xor_sync(0xffffffffu, p, 2);
                if (t == 0)
                    atomicAdd(&Cout[m0 + wm * 32 + ms * 16 + rp * 8 + g], p);
            }
        }
    }
}

// ---- launch ----
extern "C" void kernel_launch(void* const* d_in, const int* in_sizes, int n_in,
                              void* d_out, int out_size) {
    const float* structures = (const float*)d_in[0];
    const float* E  = (const float*)d_in[1];
    const float* W1 = (const float*)d_in[2];
    const float* b1 = (const float*)d_in[3];
    const float* W2 = (const float*)d_in[4];
    const float* b2 = (const float*)d_in[5];
    const float* W3 = (const float*)d_in[6];
    const float* b3 = (const float*)d_in[7];
    float* out = (float*)d_out;

    __half *feat, *h1, *w1t, *w2t;
    cudaGetSymbolAddress((void**)&feat, g_feat);
    cudaGetSymbolAddress((void**)&h1,   g_h1);
    cudaGetSymbolAddress((void**)&w1t,  g_w1t);
    cudaGetSymbolAddress((void**)&w2t,  g_w2t);

    cudaFuncSetAttribute(gemm_kernel<0>, cudaFuncAttributeMaxDynamicSharedMemorySize, SMEM_BYTES);
    cudaFuncSetAttribute(gemm_kernel<1>, cudaFuncAttributeMaxDynamicSharedMemorySize, SMEM_BYTES);

    prep_w1t_kernel<<<(HID * KF + 255) / 256, 256>>>(W1, w1t);
    prep_w2t_kernel<<<(HID * HID + 255) / 256, 256>>>(W2, w2t);
    init_out_kernel<<<(BSZ + 255) / 256, 256>>>(out, b3);
    feat_kernel<<<(BSZ * 32 + 255) / 256, 256>>>(structures, E, feat);

    dim3 grid(HID / BN, BSZ / BM);   // (8, 1024)
    gemm_kernel<0><<<grid, 256, SMEM_BYTES>>>(feat, KF, KF, w1t, b1, nullptr, (void*)h1);
    gemm_kernel<1><<<grid, 256, SMEM_BYTES>>>(h1, HID, HID, w2t, b2, W3, (void*)out);
}

// round 12
// speedup vs baseline: 1.0731x; 1.0022x over previous
#include <cuda_runtime.h>
#include <cuda_fp16.h>
#include <math.h>
#include <stdint.h>

#define BSZ 131072
#define TTR 10
#define KF 320          // padded feature dim (300 -> 320)
#define HID 1024
#define NUM_ELEM 118

// ---- scratch (device globals; no runtime allocation) ----
__device__ __half g_feat[(size_t)BSZ * KF];
__device__ __half g_h1[(size_t)BSZ * HID];
__device__ __half g_w1t[(size_t)HID * KF];    // W1^T [n][k], zero-padded
__device__ __half g_w2t[(size_t)HID * HID];   // W2^T [n][k]
__device__ uint32_t g_sEu[NUM_ELEM * 5];      // E rows packed as half2 (5 u32/row)

// ---- helpers ----
__device__ __forceinline__ void mma16(float* c, const uint32_t* a,
                                      uint32_t b0, uint32_t b1) {
    asm volatile(
        "mma.sync.aligned.m16n8k16.row.col.f32.f16.f16.f32 "
        "{%0,%1,%2,%3}, {%4,%5,%6,%7}, {%8,%9}, {%0,%1,%2,%3};"
        : "+f"(c[0]), "+f"(c[1]), "+f"(c[2]), "+f"(c[3])
        : "r"(a[0]), "r"(a[1]), "r"(a[2]), "r"(a[3]), "r"(b0), "r"(b1));
}
__device__ __forceinline__ void ldsm4(uint32_t* r, uint32_t addr) {
    asm volatile("ldmatrix.sync.aligned.m8n8.x4.shared.b16 {%0,%1,%2,%3}, [%4];"
                 : "=r"(r[0]), "=r"(r[1]), "=r"(r[2]), "=r"(r[3]) : "r"(addr));
}
__device__ __forceinline__ void cp16(uint32_t dst, const void* src) {
    asm volatile("cp.async.cg.shared.global [%0], [%1], 16;" :: "r"(dst), "l"(src));
}
#define CP_COMMIT() asm volatile("cp.async.commit_group;")
#define CP_WAIT1()  asm volatile("cp.async.wait_group 1;")
#define CP_WAIT0()  asm volatile("cp.async.wait_group 0;")

// ---- prep: tiled transposes (coalesced both sides) ----
__global__ void prep_w1t_kernel(const float* __restrict__ W1, __half* __restrict__ w1t) {
    __shared__ float tile[32][33];
    int bx = blockIdx.x;            // n-tile (32 of them)
    int by = blockIdx.y;            // k-tile (10 of them, k up to 320)
    int x = threadIdx.x, y = threadIdx.y;
    #pragma unroll
    for (int j = 0; j < 4; j++) {
        int k = by * 32 + y + j * 8;
        tile[y + j * 8][x] = (k < 300) ? W1[(size_t)k * HID + bx * 32 + x] : 0.0f;
    }
    __syncthreads();
    #pragma unroll
    for (int j = 0; j < 4; j++) {
        int n = bx * 32 + y + j * 8;
        w1t[(size_t)n * KF + by * 32 + x] = __float2half(tile[x][y + j * 8]);
    }
}
__global__ void prep_w2t_kernel(const float* __restrict__ W2, __half* __restrict__ w2t) {
    __shared__ float tile[32][33];
    int bx = blockIdx.x;            // n-tile
    int by = blockIdx.y;            // k-tile
    int x = threadIdx.x, y = threadIdx.y;
    #pragma unroll
    for (int j = 0; j < 4; j++)
        tile[y + j * 8][x] = W2[(size_t)(by * 32 + y + j * 8) * HID + bx * 32 + x];
    __syncthreads();
    #pragma unroll
    for (int j = 0; j < 4; j++)
        w2t[(size_t)(bx * 32 + y + j * 8) * HID + by * 32 + x] =
            __float2half(tile[x][y + j * 8]);
}

// ---- init output with b3; pack E rows into half2 u32 lookup ----
__global__ void init_misc_kernel(float* __restrict__ out, const float* __restrict__ b3,
                                 const float* __restrict__ E) {
    int i = blockIdx.x * blockDim.x + threadIdx.x;
    if (i < BSZ) out[i] = b3[0];
    if (i < NUM_ELEM * 5) {
        int n = i / 5, c = i - n * 5;
        __half2 h = __floats2half2_rn(E[n * 10 + 2 * c], E[n * 10 + 2 * c + 1]);
        g_sEu[i] = *(uint32_t*)&h;
    }
}

// ---- features: one thread per (row, triplet); 2 MUFU via RBF recurrence ----
// rbf_c = exp(-(0.7(c+1)-d)^2);  rbf_c = rbf_{c-1} * f,  f *= exp(-0.98),
// f_init = exp(1.4d - 1.47).  exp(-0.98) = 0.3753111 (exact to fp32).
__global__ void feat_kernel(const float* __restrict__ structures,
                            __half* __restrict__ feat) {
    __shared__ uint32_t sEu[NUM_ELEM * 5];
    for (int i = threadIdx.x; i < NUM_ELEM * 5; i += blockDim.x) sEu[i] = g_sEu[i];
    __syncthreads();

    int idx = blockIdx.x * blockDim.x + threadIdx.x;
    if (idx >= BSZ * TTR) return;
    int b = idx / TTR;
    int t = idx - b * TTR;

    const float* s = structures + (size_t)idx * 3;
    float s0 = s[0], s1 = s[1], d = s[2];
    int ii = (int)s0;
    int jj = (int)s1;

    uint32_t* o = (uint32_t*)((char*)feat + (size_t)b * (KF * 2) + t * 60);

    #pragma unroll
    for (int c = 0; c < 5; c++) o[c] = ii ? sEu[ii * 5 + c] : 0u;
    #pragma unroll
    for (int c = 0; c < 5; c++) o[5 + c] = jj ? sEu[jj * 5 + c] : 0u;

    float rb[10];
    float df = 0.7f - d;
    float r = __expf(-df * df);
    float f = __expf(1.4f * d - 1.47f);
    rb[0] = r;
    #pragma unroll
    for (int c = 1; c < 10; c++) {
        r *= f;
        rb[c] = r;
        f *= 0.37531110f;       // exp(-0.98)
    }
    if (!ii) {
        #pragma unroll
        for (int c = 0; c < 10; c++) rb[c] = 0.0f;
    }
    #pragma unroll
    for (int p = 0; p < 5; p++) {
        __half2 h = __floats2half2_rn(rb[2 * p], rb[2 * p + 1]);
        o[10 + p] = *(uint32_t*)&h;
    }
    if (t == 0) {   // zero padding columns 300..319
        uint32_t* z = (uint32_t*)((char*)feat + (size_t)b * (KF * 2) + 600);
        #pragma unroll
        for (int p = 0; p < 10; p++) z[p] = 0u;
    }
}

// ---- fp16 GEMM: BM=BN=128, warp 32x64, 2 CTAs/SM, 3-stage, reg-pipelined ----
// (UNCHANGED from Round 11 best — do not touch)
#define BM 128
#define BN 128
#define BK 64
#define RSTR 144
#define ASTAGE (BM * RSTR)
#define BSTAGE (BN * RSTR)
#define STAGE (ASTAGE + BSTAGE)
#define NSTG 3
#define SMEM_BYTES (NSTG * STAGE + 2 * BN * 4)

template <int EPI>
__global__ void __launch_bounds__(256, 2) gemm_kernel(
    const __half* __restrict__ A, int lda, int K,
    const __half* __restrict__ Bt,
    const float* __restrict__ bias,
    const float* __restrict__ W3,
    void* __restrict__ CoutV)
{
    extern __shared__ char smem[];
    uint32_t sbase;
    asm("{ .reg .u64 t; cvta.to.shared.u64 t, %1; cvt.u32.u64 %0, t; }"
        : "=r"(sbase) : "l"(smem));
    float* sBias = (float*)(smem + NSTG * STAGE);
    float* sW3   = sBias + BN;

    const int tid  = threadIdx.x;
    const int lane = tid & 31;
    const int wid  = tid >> 5;
    const int wm   = wid & 3;
    const int wn   = wid >> 2;
    const int g    = lane >> 2;
    const int t    = lane & 3;
    const int lr   = lane & 7;
    const int m0   = blockIdx.y * BM;
    const int n0   = blockIdx.x * BN;

    float acc[2][8][4];
    #pragma unroll
    for (int i = 0; i < 2; i++)
        #pragma unroll
        for (int j = 0; j < 8; j++)
            #pragma unroll
            for (int k = 0; k < 4; k++) acc[i][j][k] = 0.0f;

    const int KT = K / BK;

    auto issue = [&](int kt, int buf) {
        int k0 = kt * BK;
        uint32_t ab = sbase + buf * STAGE;
        uint32_t bb = ab + ASTAGE;
        #pragma unroll
        for (int i = 0; i < 4; i++) {
            int idx = tid + (i << 8);
            int row = idx >> 3, c = idx & 7;
            cp16(ab + row * RSTR + c * 16,
                 A + (size_t)(m0 + row) * lda + k0 + c * 8);
        }
        #pragma unroll
        for (int i = 0; i < 4; i++) {
            int idx = tid + (i << 8);
            int row = idx >> 3, c = idx & 7;
            cp16(bb + row * RSTR + c * 16,
                 Bt + (size_t)(n0 + row) * K + k0 + c * 8);
        }
    };

    auto compute = [&](int buf) {
        uint32_t ab = sbase + buf * STAGE;
        uint32_t bb = ab + ASTAGE;

        auto lda_ = [&](uint32_t* r, int ms, int ks) {
            int row = wm * 32 + ms * 16 + lr + ((lane >> 3) & 1) * 8;
            int ch  = ks * 2 + (lane >> 4);
            ldsm4(r, ab + row * RSTR + ch * 16);
        };
        auto ldb_ = [&](uint32_t* r, int np, int ks) {
            int row = wn * 64 + np * 16 + lr + (lane >> 4) * 8;
            int ch  = ks * 2 + ((lane >> 3) & 1);
            ldsm4(r, bb + row * RSTR + ch * 16);
        };

        uint32_t a[2][4], an[2][4];
        uint32_t bc[4], bn[4];

        lda_(a[0], 0, 0); lda_(a[1], 1, 0);
        ldb_(bc, 0, 0);

        #pragma unroll
        for (int ks = 0; ks < 4; ks++) {
            #pragma unroll
            for (int np = 0; np < 4; np++) {
                if (np < 3)            ldb_(bn, np + 1, ks);
                else if (ks < 3)       ldb_(bn, 0, ks + 1);
                if (np == 0 && ks < 3) { lda_(an[0], 0, ks + 1); lda_(an[1], 1, ks + 1); }

                mma16(acc[0][2 * np],     a[0], bc[0], bc[1]);
                mma16(acc[0][2 * np + 1], a[0], bc[2], bc[3]);
                mma16(acc[1][2 * np],     a[1], bc[0], bc[1]);
                mma16(acc[1][2 * np + 1], a[1], bc[2], bc[3]);

                if (!(ks == 3 && np == 3)) {
                    bc[0] = bn[0]; bc[1] = bn[1]; bc[2] = bn[2]; bc[3] = bn[3];
                }
            }
            if (ks < 3) {
                #pragma unroll
                for (int q = 0; q < 4; q++) { a[0][q] = an[0][q]; a[1][q] = an[1][q]; }
            }
        }
    };

    issue(0, 0); CP_COMMIT();
    issue(1, 1); CP_COMMIT();

    for (int kt = 0; kt < KT; kt++) {
        int cur = kt - (kt / NSTG) * NSTG;
        if (kt + 1 < KT) CP_WAIT1(); else CP_WAIT0();
        __syncthreads();
        if (kt + 2 < KT) {
            int nb = kt + 2;
            issue(nb, nb - (nb / NSTG) * NSTG);
            CP_COMMIT();
        }
        compute(cur);
    }

    for (int i = tid; i < BN; i += 256) {
        sBias[i] = bias[n0 + i];
        if (EPI == 1) sW3[i] = W3[n0 + i];
    }
    __syncthreads();

    if (EPI == 0) {
        __half* Cout = (__half*)CoutV;
        #pragma unroll
        for (int ms = 0; ms < 2; ms++) {
            int row = m0 + wm * 32 + ms * 16 + g;
            #pragma unroll
            for (int ns = 0; ns < 8; ns++) {
                int cl  = wn * 64 + ns * 8 + t * 2;
                int col = n0 + cl;
                __half2 v0 = __floats2half2_rn(
                    fmaxf(acc[ms][ns][0] + sBias[cl],     0.0f),
                    fmaxf(acc[ms][ns][1] + sBias[cl + 1], 0.0f));
                __half2 v1 = __floats2half2_rn(
                    fmaxf(acc[ms][ns][2] + sBias[cl],     0.0f),
                    fmaxf(acc[ms][ns][3] + sBias[cl + 1], 0.0f));
                *(__half2*)&Cout[(size_t)row * HID + col]       = v0;
                *(__half2*)&Cout[(size_t)(row + 8) * HID + col] = v1;
            }
        }
    } else {
        float* Cout = (float*)CoutV;
        float racc[2][2] = {{0.0f, 0.0f}, {0.0f, 0.0f}};
        #pragma unroll
        for (int ms = 0; ms < 2; ms++) {
            #pragma unroll
            for (int ns = 0; ns < 8; ns++) {
                int cl = wn * 64 + ns * 8 + t * 2;
                racc[ms][0] += fmaxf(acc[ms][ns][0] + sBias[cl],     0.0f) * sW3[cl]
                             + fmaxf(acc[ms][ns][1] + sBias[cl + 1], 0.0f) * sW3[cl + 1];
                racc[ms][1] += fmaxf(acc[ms][ns][2] + sBias[cl],     0.0f) * sW3[cl]
                             + fmaxf(acc[ms][ns][3] + sBias[cl + 1], 0.0f) * sW3[cl + 1];
            }
        }
        #pragma unroll
        for (int ms = 0; ms < 2; ms++) {
            #pragma unroll
            for (int rp = 0; rp < 2; rp++) {
                float p = racc[ms][rp];
                p += __shfl_xor_sync(0xffffffffu, p, 1);
                p += __shfl_xor_sync(0xffffffffu, p, 2);
                if (t == 0)
                    atomicAdd(&Cout[m0 + wm * 32 + ms * 16 + rp * 8 + g], p);
            }
        }
    }
}

// ---- launch ----
extern "C" void kernel_launch(void* const* d_in, const int* in_sizes, int n_in,
                              void* d_out, int out_size) {
    const float* structures = (const float*)d_in[0];
    const float* E  = (const float*)d_in[1];
    const float* W1 = (const float*)d_in[2];
    const float* b1 = (const float*)d_in[3];
    const float* W2 = (const float*)d_in[4];
    const float* b2 = (const float*)d_in[5];
    const float* W3 = (const float*)d_in[6];
    const float* b3 = (const float*)d_in[7];
    float* out = (float*)d_out;

    __half *feat, *h1, *w1t, *w2t;
    cudaGetSymbolAddress((void**)&feat, g_feat);
    cudaGetSymbolAddress((void**)&h1,   g_h1);
    cudaGetSymbolAddress((void**)&w1t,  g_w1t);
    cudaGetSymbolAddress((void**)&w2t,  g_w2t);

    cudaFuncSetAttribute(gemm_kernel<0>, cudaFuncAttributeMaxDynamicSharedMemorySize, SMEM_BYTES);
    cudaFuncSetAttribute(gemm_kernel<1>, cudaFuncAttributeMaxDynamicSharedMemorySize, SMEM_BYTES);

    prep_w1t_kernel<<<dim3(32, 10), dim3(32, 8)>>>(W1, w1t);
    prep_w2t_kernel<<<dim3(32, 32), dim3(32, 8)>>>(W2, w2t);
    init_misc_kernel<<<(BSZ + 255) / 256, 256>>>(out, b3, E);
    feat_kernel<<<(BSZ * TTR + 255) / 256, 256>>>(structures, feat);

    dim3 grid(HID / BN, BSZ / BM);   // (8, 1024)
    gemm_kernel<0><<<grid, 256, SMEM_BYTES>>>(feat, KF, KF, w1t, b1, nullptr, (void*)h1);
    gemm_kernel<1><<<grid, 256, SMEM_BYTES>>>(h1, HID, HID, w2t, b2, W3, (void*)out);
}

// round 14
// speedup vs baseline: 1.1297x; 1.0527x over previous
#include <cuda_runtime.h>
#include <cuda_fp16.h>
#include <math.h>
#include <stdint.h>

#define BSZ 131072
#define TTR 10
#define KF 320          // padded feature dim (300 -> 320)
#define HID 1024
#define NUM_ELEM 118

// ---- scratch (device globals; no runtime allocation) ----
__device__ __half g_feat[(size_t)BSZ * KF];
__device__ __half g_h1[(size_t)BSZ * HID];
__device__ __half g_w1t[(size_t)HID * KF];    // W1^T [n][k], zero-padded
__device__ __half g_w2t[(size_t)HID * HID];   // W2^T [n][k]
__device__ uint32_t g_sEu[NUM_ELEM * 5];      // E rows packed as half2 (5 u32/row)

// ---- helpers ----
__device__ __forceinline__ void mma16(float* c, const uint32_t* a,
                                      uint32_t b0, uint32_t b1) {
    asm volatile(
        "mma.sync.aligned.m16n8k16.row.col.f32.f16.f16.f32 "
        "{%0,%1,%2,%3}, {%4,%5,%6,%7}, {%8,%9}, {%0,%1,%2,%3};"
        : "+f"(c[0]), "+f"(c[1]), "+f"(c[2]), "+f"(c[3])
        : "r"(a[0]), "r"(a[1]), "r"(a[2]), "r"(a[3]), "r"(b0), "r"(b1));
}
__device__ __forceinline__ void ldsm4(uint32_t* r, uint32_t addr) {
    asm volatile("ldmatrix.sync.aligned.m8n8.x4.shared.b16 {%0,%1,%2,%3}, [%4];"
                 : "=r"(r[0]), "=r"(r[1]), "=r"(r[2]), "=r"(r[3]) : "r"(addr));
}
__device__ __forceinline__ void cp16(uint32_t dst, const void* src) {
    asm volatile("cp.async.cg.shared.global [%0], [%1], 16;" :: "r"(dst), "l"(src));
}
#define CP_COMMIT() asm volatile("cp.async.commit_group;")
#define CP_WAIT1()  asm volatile("cp.async.wait_group 1;")
#define CP_WAIT0()  asm volatile("cp.async.wait_group 0;")

// ---- prep: tiled transposes (coalesced both sides) ----
__global__ void prep_w1t_kernel(const float* __restrict__ W1, __half* __restrict__ w1t) {
    __shared__ float tile[32][33];
    int bx = blockIdx.x, by = blockIdx.y;
    int x = threadIdx.x, y = threadIdx.y;
    #pragma unroll
    for (int j = 0; j < 4; j++) {
        int k = by * 32 + y + j * 8;
        tile[y + j * 8][x] = (k < 300) ? W1[(size_t)k * HID + bx * 32 + x] : 0.0f;
    }
    __syncthreads();
    #pragma unroll
    for (int j = 0; j < 4; j++) {
        int n = bx * 32 + y + j * 8;
        w1t[(size_t)n * KF + by * 32 + x] = __float2half(tile[x][y + j * 8]);
    }
}
__global__ void prep_w2t_kernel(const float* __restrict__ W2, __half* __restrict__ w2t) {
    __shared__ float tile[32][33];
    int bx = blockIdx.x, by = blockIdx.y;
    int x = threadIdx.x, y = threadIdx.y;
    #pragma unroll
    for (int j = 0; j < 4; j++)
        tile[y + j * 8][x] = W2[(size_t)(by * 32 + y + j * 8) * HID + bx * 32 + x];
    __syncthreads();
    #pragma unroll
    for (int j = 0; j < 4; j++)
        w2t[(size_t)(bx * 32 + y + j * 8) * HID + by * 32 + x] =
            __float2half(tile[x][y + j * 8]);
}

// ---- init output with b3; pack E rows into half2 u32 lookup ----
__global__ void init_misc_kernel(float* __restrict__ out, const float* __restrict__ b3,
                                 const float* __restrict__ E) {
    int i = blockIdx.x * blockDim.x + threadIdx.x;
    if (i < BSZ) out[i] = b3[0];
    if (i < NUM_ELEM * 5) {
        int n = i / 5, c = i - n * 5;
        __half2 h = __floats2half2_rn(E[n * 10 + 2 * c], E[n * 10 + 2 * c + 1]);
        g_sEu[i] = *(uint32_t*)&h;
    }
}

// ---- features: 320 threads / 32 rows per block; smem-staged, fully coalesced ----
#define FROWS 32
#define FTHREADS (FROWS * TTR)           // 320
__global__ void __launch_bounds__(FTHREADS) feat_kernel(
    const float* __restrict__ structures, __half* __restrict__ feat) {
    __shared__ uint32_t sEu[NUM_ELEM * 5];
    __shared__ __align__(16) float    sS[FROWS * 30];   // staged structures
    __shared__ __align__(16) uint32_t sF[FROWS * 160];  // staged output rows

    int tid = threadIdx.x;
    for (int i = tid; i < NUM_ELEM * 5; i += FTHREADS) sEu[i] = g_sEu[i];

    size_t base_row = (size_t)blockIdx.x * FROWS;
    // coalesced load of 32 rows x 30 floats
    #pragma unroll
    for (int i = 0; i < 3; i++)
        sS[tid + i * FTHREADS] = structures[base_row * 30 + tid + i * FTHREADS];
    __syncthreads();

    int r = tid / TTR;            // local row 0..31
    int t = tid - r * TTR;        // triplet 0..9

    float s0 = sS[r * 30 + t * 3];
    float s1 = sS[r * 30 + t * 3 + 1];
    float d  = sS[r * 30 + t * 3 + 2];
    int ii = (int)s0;
    int jj = (int)s1;

    uint32_t* o = &sF[r * 160 + t * 15];
    #pragma unroll
    for (int c = 0; c < 5; c++) o[c] = ii ? sEu[ii * 5 + c] : 0u;
    #pragma unroll
    for (int c = 0; c < 5; c++) o[5 + c] = jj ? sEu[jj * 5 + c] : 0u;

    // RBF recurrence: 2 MUFU per triplet
    float rb[10];
    float df = 0.7f - d;
    float rv = __expf(-df * df);
    float f  = __expf(1.4f * d - 1.47f);
    rb[0] = rv;
    #pragma unroll
    for (int c = 1; c < 10; c++) {
        rv *= f;
        rb[c] = rv;
        f *= 0.37531110f;         // exp(-0.98)
    }
    if (!ii) {
        #pragma unroll
        for (int c = 0; c < 10; c++) rb[c] = 0.0f;
    }
    #pragma unroll
    for (int p = 0; p < 5; p++) {
        __half2 h = __floats2half2_rn(rb[2 * p], rb[2 * p + 1]);
        o[10 + p] = *(uint32_t*)&h;
    }
    if (t == 0) {                 // zero padding columns 300..319
        #pragma unroll
        for (int p = 0; p < 10; p++) sF[r * 160 + 150 + p] = 0u;
    }
    __syncthreads();

    // coalesced flush: 32 rows x 640B = 1280 uint4
    const uint4* src = (const uint4*)sF;
    uint4* dst = (uint4*)(feat + base_row * KF);
    #pragma unroll
    for (int i = 0; i < 4; i++)
        dst[tid + i * FTHREADS] = src[tid + i * FTHREADS];
}

// ---- fp16 GEMM: BM=BN=128, warp 32x64, 2 CTAs/SM, 3-stage, reg-pipelined ----
// (UNCHANGED from Round 11 best — do not touch)
#define BM 128
#define BN 128
#define BK 64
#define RSTR 144
#define ASTAGE (BM * RSTR)
#define BSTAGE (BN * RSTR)
#define STAGE (ASTAGE + BSTAGE)
#define NSTG 3
#define SMEM_BYTES (NSTG * STAGE + 2 * BN * 4)

template <int EPI>
__global__ void __launch_bounds__(256, 2) gemm_kernel(
    const __half* __restrict__ A, int lda, int K,
    const __half* __restrict__ Bt,
    const float* __restrict__ bias,
    const float* __restrict__ W3,
    void* __restrict__ CoutV)
{
    extern __shared__ char smem[];
    uint32_t sbase;
    asm("{ .reg .u64 t; cvta.to.shared.u64 t, %1; cvt.u32.u64 %0, t; }"
        : "=r"(sbase) : "l"(smem));
    float* sBias = (float*)(smem + NSTG * STAGE);
    float* sW3   = sBias + BN;

    const int tid  = threadIdx.x;
    const int lane = tid & 31;
    const int wid  = tid >> 5;
    const int wm   = wid & 3;
    const int wn   = wid >> 2;
    const int g    = lane >> 2;
    const int t    = lane & 3;
    const int lr   = lane & 7;
    const int m0   = blockIdx.y * BM;
    const int n0   = blockIdx.x * BN;

    float acc[2][8][4];
    #pragma unroll
    for (int i = 0; i < 2; i++)
        #pragma unroll
        for (int j = 0; j < 8; j++)
            #pragma unroll
            for (int k = 0; k < 4; k++) acc[i][j][k] = 0.0f;

    const int KT = K / BK;

    auto issue = [&](int kt, int buf) {
        int k0 = kt * BK;
        uint32_t ab = sbase + buf * STAGE;
        uint32_t bb = ab + ASTAGE;
        #pragma unroll
        for (int i = 0; i < 4; i++) {
            int idx = tid + (i << 8);
            int row = idx >> 3, c = idx & 7;
            cp16(ab + row * RSTR + c * 16,
                 A + (size_t)(m0 + row) * lda + k0 + c * 8);
        }
        #pragma unroll
        for (int i = 0; i < 4; i++) {
            int idx = tid + (i << 8);
            int row = idx >> 3, c = idx & 7;
            cp16(bb + row * RSTR + c * 16,
                 Bt + (size_t)(n0 + row) * K + k0 + c * 8);
        }
    };

    auto compute = [&](int buf) {
        uint32_t ab = sbase + buf * STAGE;
        uint32_t bb = ab + ASTAGE;

        auto lda_ = [&](uint32_t* r, int ms, int ks) {
            int row = wm * 32 + ms * 16 + lr + ((lane >> 3) & 1) * 8;
            int ch  = ks * 2 + (lane >> 4);
            ldsm4(r, ab + row * RSTR + ch * 16);
        };
        auto ldb_ = [&](uint32_t* r, int np, int ks) {
            int row = wn * 64 + np * 16 + lr + (lane >> 4) * 8;
            int ch  = ks * 2 + ((lane >> 3) & 1);
            ldsm4(r, bb + row * RSTR + ch * 16);
        };

        uint32_t a[2][4], an[2][4];
        uint32_t bc[4], bn[4];

        lda_(a[0], 0, 0); lda_(a[1], 1, 0);
        ldb_(bc, 0, 0);

        #pragma unroll
        for (int ks = 0; ks < 4; ks++) {
            #pragma unroll
            for (int np = 0; np < 4; np++) {
                if (np < 3)            ldb_(bn, np + 1, ks);
                else if (ks < 3)       ldb_(bn, 0, ks + 1);
                if (np == 0 && ks < 3) { lda_(an[0], 0, ks + 1); lda_(an[1], 1, ks + 1); }

                mma16(acc[0][2 * np],     a[0], bc[0], bc[1]);
                mma16(acc[0][2 * np + 1], a[0], bc[2], bc[3]);
                mma16(acc[1][2 * np],     a[1], bc[0], bc[1]);
                mma16(acc[1][2 * np + 1], a[1], bc[2], bc[3]);

                if (!(ks == 3 && np == 3)) {
                    bc[0] = bn[0]; bc[1] = bn[1]; bc[2] = bn[2]; bc[3] = bn[3];
                }
            }
            if (ks < 3) {
                #pragma unroll
                for (int q = 0; q < 4; q++) { a[0][q] = an[0][q]; a[1][q] = an[1][q]; }
            }
        }
    };

    issue(0, 0); CP_COMMIT();
    issue(1, 1); CP_COMMIT();

    for (int kt = 0; kt < KT; kt++) {
        int cur = kt - (kt / NSTG) * NSTG;
        if (kt + 1 < KT) CP_WAIT1(); else CP_WAIT0();
        __syncthreads();
        if (kt + 2 < KT) {
            int nb = kt + 2;
            issue(nb, nb - (nb / NSTG) * NSTG);
            CP_COMMIT();
        }
        compute(cur);
    }

    for (int i = tid; i < BN; i += 256) {
        sBias[i] = bias[n0 + i];
        if (EPI == 1) sW3[i] = W3[n0 + i];
    }
    __syncthreads();

    if (EPI == 0) {
        __half* Cout = (__half*)CoutV;
        #pragma unroll
        for (int ms = 0; ms < 2; ms++) {
            int row = m0 + wm * 32 + ms * 16 + g;
            #pragma unroll
            for (int ns = 0; ns < 8; ns++) {
                int cl  = wn * 64 + ns * 8 + t * 2;
                int col = n0 + cl;
                __half2 v0 = __floats2half2_rn(
                    fmaxf(acc[ms][ns][0] + sBias[cl],     0.0f),
                    fmaxf(acc[ms][ns][1] + sBias[cl + 1], 0.0f));
                __half2 v1 = __floats2half2_rn(
                    fmaxf(acc[ms][ns][2] + sBias[cl],     0.0f),
                    fmaxf(acc[ms][ns][3] + sBias[cl + 1], 0.0f));
                *(__half2*)&Cout[(size_t)row * HID + col]       = v0;
                *(__half2*)&Cout[(size_t)(row + 8) * HID + col] = v1;
            }
        }
    } else {
        float* Cout = (float*)CoutV;
        float racc[2][2] = {{0.0f, 0.0f}, {0.0f, 0.0f}};
        #pragma unroll
        for (int ms = 0; ms < 2; ms++) {
            #pragma unroll
            for (int ns = 0; ns < 8; ns++) {
                int cl = wn * 64 + ns * 8 + t * 2;
                racc[ms][0] += fmaxf(acc[ms][ns][0] + sBias[cl],     0.0f) * sW3[cl]
                             + fmaxf(acc[ms][ns][1] + sBias[cl + 1], 0.0f) * sW3[cl + 1];
                racc[ms][1] += fmaxf(acc[ms][ns][2] + sBias[cl],     0.0f) * sW3[cl]
                             + fmaxf(acc[ms][ns][3] + sBias[cl + 1], 0.0f) * sW3[cl + 1];
            }
        }
        #pragma unroll
        for (int ms = 0; ms < 2; ms++) {
            #pragma unroll
            for (int rp = 0; rp < 2; rp++) {
                float p = racc[ms][rp];
                p += __shfl_xor_sync(0xffffffffu, p, 1);
                p += __shfl_xor_sync(0xffffffffu, p, 2);
                if (t == 0)
                    atomicAdd(&Cout[m0 + wm * 32 + ms * 16 + rp * 8 + g], p);
            }
        }
    }
}

// ---- launch ----
extern "C" void kernel_launch(void* const* d_in, const int* in_sizes, int n_in,
                              void* d_out, int out_size) {
    const float* structures = (const float*)d_in[0];
    const float* E  = (const float*)d_in[1];
    const float* W1 = (const float*)d_in[2];
    const float* b1 = (const float*)d_in[3];
    const float* W2 = (const float*)d_in[4];
    const float* b2 = (const float*)d_in[5];
    const float* W3 = (const float*)d_in[6];
    const float* b3 = (const float*)d_in[7];
    float* out = (float*)d_out;

    __half *feat, *h1, *w1t, *w2t;
    cudaGetSymbolAddress((void**)&feat, g_feat);
    cudaGetSymbolAddress((void**)&h1,   g_h1);
    cudaGetSymbolAddress((void**)&w1t,  g_w1t);
    cudaGetSymbolAddress((void**)&w2t,  g_w2t);

    cudaFuncSetAttribute(gemm_kernel<0>, cudaFuncAttributeMaxDynamicSharedMemorySize, SMEM_BYTES);
    cudaFuncSetAttribute(gemm_kernel<1>, cudaFuncAttributeMaxDynamicSharedMemorySize, SMEM_BYTES);

    prep_w1t_kernel<<<dim3(32, 10), dim3(32, 8)>>>(W1, w1t);
    prep_w2t_kernel<<<dim3(32, 32), dim3(32, 8)>>>(W2, w2t);
    init_misc_kernel<<<(BSZ + 255) / 256, 256>>>(out, b3, E);
    feat_kernel<<<BSZ / FROWS, FTHREADS>>>(structures, feat);

    dim3 grid(HID / BN, BSZ / BM);   // (8, 1024)
    gemm_kernel<0><<<grid, 256, SMEM_BYTES>>>(feat, KF, KF, w1t, b1, nullptr, (void*)h1);
    gemm_kernel<1><<<grid, 256, SMEM_BYTES>>>(h1, HID, HID, w2t, b2, W3, (void*)out);
}